// round 2
// baseline (speedup 1.0000x reference)
#include <cuda_runtime.h>
#include <cstdint>

#define B_      16
#define NCLS_   3
#define CREG_   50
#define H_      96
#define W_      320
#define HW_     (H_*W_)          // 30720
#define TOT_    (B_*NCLS_*HW_)   // 1474560
#define K_      100
#define CAP_    24576
#define SURV_   4096
#define NOUT_   13
#define THRESH_ 0.2f
#define EPS_    1e-6f
// sigmoid(x) >= 0.2  <=>  x >= -ln(4) = -1.3862944; prefilter with margin
#define RAW_PRE (-1.39f)

static __device__ unsigned long long g_cand[B_][CAP_];
static __device__ int                g_cnt[B_];
static __device__ unsigned long long g_sel[B_*K_];
static __device__ int                g_selcnt[B_];

__device__ __forceinline__ float sigf(float x) { return 1.0f / (1.0f + expf(-x)); }

// ---------------- init: zero per-batch counters ----------------
__global__ void k_init() {
    int i = threadIdx.x;
    if (i < B_) g_cnt[i] = 0;
}

// ---------------- fused sigmoid + 3x3 NMS + threshold + collect ----------------
__global__ void k_nms(const float* __restrict__ hmp) {
    int idx = blockIdx.x * blockDim.x + threadIdx.x;
    if (idx >= TOT_) return;
    float raw = __ldg(&hmp[idx]);
    if (raw < RAW_PRE) return;               // conservative raw-logit prefilter
    float s = sigf(raw);
    if (!(s >= THRESH_)) return;             // exact threshold in sigmoid space
    int r   = idx % (NCLS_*HW_);
    int b   = idx / (NCLS_*HW_);
    int c   = r / HW_;
    int ind = r % HW_;
    int y   = ind / W_;
    int x   = ind % W_;
    // keep iff no neighbor's sigmoid is strictly greater (matches hmax==heat,
    // including equal-after-sigmoid ties kept by the reference)
    #pragma unroll
    for (int dy = -1; dy <= 1; ++dy) {
        int yy = y + dy;
        if (yy < 0 || yy >= H_) continue;
        #pragma unroll
        for (int dx = -1; dx <= 1; ++dx) {
            if (dy == 0 && dx == 0) continue;
            int xx = x + dx;
            if (xx < 0 || xx >= W_) continue;
            float sn = sigf(__ldg(&hmp[idx + dy*W_ + dx]));
            if (sn > s) return;
        }
    }
    unsigned lo = 0xFFFFFFFFu - (unsigned)(c * HW_ + ind);   // smaller (class,ind) -> larger lo
    unsigned long long key = ((unsigned long long)__float_as_uint(s) << 32) | lo;
    int pos = atomicAdd(&g_cnt[b], 1);
    if (pos < CAP_) g_cand[b][pos] = key;
}

// ---------------- per-batch top-100 select (histogram narrow + bitonic) ----------------
__global__ void k_select(void) {
    const int b   = blockIdx.x;
    const int tid = threadIdx.x;            // 256 threads
    __shared__ int hist[320];
    __shared__ int subhist[256];
    __shared__ unsigned long long surv[SURV_];
    __shared__ int s_bstar, s_b2, s_scount, s_target;

    int n = g_cnt[b]; if (n > CAP_) n = CAP_;
    for (int i = tid; i < 320; i += 256) hist[i] = 0;
    for (int i = tid; i < 256; i += 256) subhist[i] = 0;
    __syncthreads();

    // coarse histogram on scoreBits>>16 (scores in [0.2,1] -> bits>>16 in [0x3E4C,0x3F80])
    for (int i = tid; i < n; i += 256) {
        int bin = (int)(unsigned)(g_cand[b][i] >> 48) - 0x3E4C;
        bin = max(0, min(319, bin));
        atomicAdd(&hist[bin], 1);
    }
    __syncthreads();
    if (tid == 0) {
        int target = n < K_ ? n : K_;
        s_target = target;
        int acc = 0, bst = 0;
        for (int i = 319; i >= 0; --i) { acc += hist[i]; if (acc >= target) { bst = i; break; } }
        s_bstar = bst;
    }
    __syncthreads();
    const int bstar = s_bstar;

    // refine within cutoff bin on next 8 bits
    for (int i = tid; i < n; i += 256) {
        unsigned long long key = g_cand[b][i];
        int bin = (int)(unsigned)(key >> 48) - 0x3E4C;
        bin = max(0, min(319, bin));
        if (bin == bstar) atomicAdd(&subhist[(unsigned)(key >> 40) & 0xFF], 1);
    }
    __syncthreads();
    if (tid == 0) {
        int cntabove = 0;
        for (int i = 319; i > bstar; --i) cntabove += hist[i];
        int m = s_target - cntabove; if (m < 1) m = 1;
        int acc = 0, b2 = 0;
        for (int s = 255; s >= 0; --s) { acc += subhist[s]; if (acc >= m) { b2 = s; break; } }
        s_b2 = b2;
        s_scount = 0;
    }
    __syncthreads();
    const int b2 = s_b2;

    // collect survivors
    for (int i = tid; i < n; i += 256) {
        unsigned long long key = g_cand[b][i];
        int bin = (int)(unsigned)(key >> 48) - 0x3E4C;
        bin = max(0, min(319, bin));
        bool take = (bin > bstar) || (bin == bstar && (int)((key >> 40) & 0xFF) >= b2);
        if (take) {
            int p = atomicAdd(&s_scount, 1);
            if (p < SURV_) surv[p] = key;
        }
    }
    __syncthreads();
    int sc = min(s_scount, SURV_);
    int P = 128; while (P < sc) P <<= 1;    // <= SURV_
    for (int i = tid; i < P; i += 256) if (i >= sc) surv[i] = 0ULL;
    __syncthreads();

    // bitonic sort descending (full 64-bit keys => exact reference tie order)
    for (int k = 2; k <= P; k <<= 1) {
        for (int j = k >> 1; j > 0; j >>= 1) {
            for (int i = tid; i < P; i += 256) {
                int ixj = i ^ j;
                if (ixj > i) {
                    bool up = ((i & k) == 0);
                    unsigned long long a = surv[i], cbb = surv[ixj];
                    if ((a < cbb) == up) { surv[i] = cbb; surv[ixj] = a; }
                }
            }
            __syncthreads();
        }
    }

    int target = s_target;
    for (int kk = tid; kk < K_; kk += 256)
        if (kk < target) g_sel[b*K_ + kk] = surv[kk];
    if (tid == 0) g_selcnt[b] = target;
}

// ---------------- final per-detection math ----------------
__global__ void k_final(const float* __restrict__ pred_reg,
                        const float* __restrict__ calib,
                        const float* __restrict__ pad_size,
                        const float* __restrict__ dim_mean,
                        float* __restrict__ out) {
    int b = blockIdx.x;
    int k = threadIdx.x;
    if (k >= K_) return;
    float* row = out + (size_t)(b*K_ + k) * NOUT_;

    if (k >= g_selcnt[b]) {
        #pragma unroll
        for (int j = 0; j < NOUT_; ++j) row[j] = 0.0f;
        return;
    }
    unsigned long long key = g_sel[b*K_ + k];
    float score  = __uint_as_float((unsigned)(key >> 32));
    unsigned lo  = 0xFFFFFFFFu - (unsigned)(key & 0xFFFFFFFFu);
    int cls = (int)(lo / HW_);
    int ind = (int)(lo % HW_);
    float fx = (float)(ind % W_);
    float fy = (float)(ind / W_);

    const float* rb = pred_reg + (size_t)b * CREG_ * HW_ + ind;
    #define PREG(j) __ldg(&rb[(j) * HW_])

    float fu = calib[b*4+0], cu = calib[b*4+1], fv = calib[b*4+2], cv = calib[b*4+3];
    float pw = pad_size[b*2+0], ph = pad_size[b*2+1];

    // 2D box
    float r0 = fmaxf(PREG(0), 0.f), r1 = fmaxf(PREG(1), 0.f);
    float r2 = fmaxf(PREG(2), 0.f), r3 = fmaxf(PREG(3), 0.f);
    const float HIX = (float)(W_*4 - 1), HIY = (float)(H_*4 - 1);
    float bx0 = fminf(fmaxf((fx - r0)*4.f - pw, 0.f), HIX);
    float by0 = fminf(fmaxf((fy - r1)*4.f - ph, 0.f), HIY);
    float bx1 = fminf(fmaxf((fx + r2)*4.f - pw, 0.f), HIX);
    float by1 = fminf(fmaxf((fy + r3)*4.f - ph, 0.f), HIY);

    // dims
    const float* dm = dim_mean + cls*3;
    float d0 = expf(PREG(6)) * dm[0];
    float d1 = expf(PREG(7)) * dm[1];
    float d2 = expf(PREG(8)) * dm[2];
    float h3d = d1;

    // keypoint y's: pois[26 + 2j], j=0..9
    float ky0 = PREG(26), ky1 = PREG(28), ky2 = PREG(30), ky3 = PREG(32);
    float ky4 = PREG(34), ky5 = PREG(36), ky6 = PREG(38), ky7 = PREG(40);
    float ky8 = PREG(42), ky9 = PREG(44);

    float fh = fu * h3d;
    float d_ctr = fh / (fmaxf(ky8 - ky9, 0.f)*4.f + EPS_);
    float d_02  = 0.5f * (fh / (fmaxf(ky0 - ky4, 0.f)*4.f + EPS_)
                        + fh / (fmaxf(ky2 - ky6, 0.f)*4.f + EPS_));
    float d_13  = 0.5f * (fh / (fmaxf(ky1 - ky5, 0.f)*4.f + EPS_)
                        + fh / (fmaxf(ky3 - ky7, 0.f)*4.f + EPS_));
    float kd0 = fminf(fmaxf(d_ctr, 0.1f), 100.f);
    float kd1 = fminf(fmaxf(d_02 , 0.1f), 100.f);
    float kd2 = fminf(fmaxf(d_13 , 0.1f), 100.f);

    float doff   = PREG(48);
    float sgd    = 1.0f / (1.0f + expf(-doff));
    float direct = fminf(fmaxf(1.0f / sgd - 1.0f, 0.1f), 100.f);

    float u0 = expf(PREG(49));
    float u1 = expf(PREG(45));
    float u2 = expf(PREG(46));
    float u3 = expf(PREG(47));
    float w0 = 1.f/u0, w1 = 1.f/u1, w2 = 1.f/u2, w3 = 1.f/u3;
    float S  = w0 + w1 + w2 + w3;
    w0 /= S; w1 /= S; w2 /= S; w3 /= S;
    float depth = direct*w0 + kd0*w1 + kd1*w2 + kd2*w3;
    float derr  = w0*u0 + w1*u1 + w2*u2 + w3*u3;

    float off0 = PREG(4), off1 = PREG(5);
    float projx = (fx + off0)*4.f - pw;
    float projy = (fy + off1)*4.f - ph;
    float x3 = (projx - cu) * depth / fu;
    float y3 = (projy - cv) * depth / fv;

    row[0]  = (float)cls;
    row[1]  = score;
    row[2]  = bx0;  row[3]  = by0;  row[4]  = bx1;  row[5]  = by1;
    row[6]  = d0;   row[7]  = d1;   row[8]  = d2;
    row[9]  = x3;   row[10] = y3;   row[11] = depth;
    row[12] = derr;
    #undef PREG
}

extern "C" void kernel_launch(void* const* d_in, const int* in_sizes, int n_in,
                              void* d_out, int out_size) {
    const float* pred_hmp = (const float*)d_in[0];
    const float* pred_reg = (const float*)d_in[1];
    const float* calib    = (const float*)d_in[2];
    const float* pad_size = (const float*)d_in[3];
    const float* dim_mean = (const float*)d_in[4];
    float* out = (float*)d_out;

    k_init<<<1, 32>>>();
    k_nms<<<(TOT_ + 255)/256, 256>>>(pred_hmp);
    k_select<<<B_, 256>>>();
    k_final<<<B_, 128>>>(pred_reg, calib, pad_size, dim_mean, out);
}